// round 15
// baseline (speedup 1.0000x reference)
#include <cuda_runtime.h>

#define BB 4
#define CC 64
#define NN 8192
#define SS 2048
#define KNBR 16
#define GG 64

#define OFF_XYZ (4*256*2048)            /* 2097152 */
#define OFF_IDX (OFF_XYZ + 4*3*2048)    /* 2121728 */

#define MUL_F32X2(out, a, b) \
    asm("mul.rn.f32x2 %0, %1, %2;" : "=l"(out) : "l"(a), "l"(b))
#define ADD_F32X2(out, a, b) \
    asm("add.rn.f32x2 %0, %1, %2;" : "=l"(out) : "l"(a), "l"(b))
#define SUB_F32X2(out, a, b) \
    asm("sub.rn.f32x2 %0, %1, %2;" : "=l"(out) : "l"(a), "l"(b))
#define PACK_F32X2(out, lo, hi) \
    asm("mov.b64 %0, {%1, %2};" : "=l"(out) : "f"(lo), "f"(hi))
#define UNPACK_F32X2(lo, hi, in) \
    asm("mov.b64 {%0, %1}, %2;" : "=f"(lo), "=f"(hi) : "l"(in))
#define REDUX_MAX_U32(d, s) \
    asm volatile("redux.sync.max.u32 %0, %1, 0xffffffff;" : "=r"(d) : "r"(s))

// ---------------- scratch (static device globals; no allocations) ----------
__device__ int   g_sidx[BB*SS];
__device__ float g_sx[BB*CC*SS];
__device__ float g_D[(size_t)BB*SS*NN];    // 256 MB distance matrix
__device__ float g_tmin[BB*SS*64];         // per-(row, 128-col tile) min (2 MB)
__device__ int   g_knn[BB*SS*KNBR];

// ============================================================================
// Kernel 1: Farthest point sampling (R12/R14 winner, verbatim). Bit-exact.
// ============================================================================
__global__ __launch_bounds__(512) void fps_kernel(const float* __restrict__ xyz,
                                                  float* __restrict__ out)
{
    extern __shared__ float4 spk[];               // [8192] packed {x,y,z,0}

    const int b    = blockIdx.x;
    const int tid  = threadIdx.x;
    const int lane = tid & 31;
    const int wid  = tid >> 5;
    const float* xb = xyz + (size_t)b * 3 * NN;

    __shared__ unsigned swmax[16];
    __shared__ int      sh_idx[2];
    __shared__ int      sidx_s[SS];               // winner log

#pragma unroll
    for (int k = 0; k < 16; k++) {
        int i = tid + 512 * k;
        float4 v;
        v.x = xb[i];
        v.y = xb[NN + i];
        v.z = xb[2*NN + i];
        v.w = 0.0f;
        spk[i] = v;
    }

    unsigned long long pxp[8], pyp[8], pzp[8];
    float dd[16];
    const float FMAX = __int_as_float(0x7F7FFFFF);
#pragma unroll
    for (int jp = 0; jp < 8; jp++) {
        int n0 = tid + 1024 * jp;
        int n1 = n0 + 512;
        PACK_F32X2(pxp[jp], xb[n0],          xb[n1]);
        PACK_F32X2(pyp[jp], xb[NN + n0],     xb[NN + n1]);
        PACK_F32X2(pzp[jp], xb[2*NN + n0],   xb[2*NN + n1]);
        dd[2*jp]     = FMAX;
        dd[2*jp + 1] = FMAX;
    }

    if (tid == 0) {
        sh_idx[0] = 0x7FFFFFFF;
        sh_idx[1] = 0x7FFFFFFF;
        sidx_s[0] = 0;
    }
    __syncthreads();

    float4 ce = spk[0];

    for (int s = 1; s < SS; s++) {
        unsigned long long cx2, cy2, cz2;
        PACK_F32X2(cx2, ce.x, ce.x);
        PACK_F32X2(cy2, ce.y, ce.y);
        PACK_F32X2(cz2, ce.z, ce.z);

        float best = 0.0f;
#pragma unroll
        for (int jp = 0; jp < 8; jp++) {
            unsigned long long dx2, dy2, dz2, sx2, sy2, sz2, s12, s22;
            SUB_F32X2(dx2, pxp[jp], cx2);
            SUB_F32X2(dy2, pyp[jp], cy2);
            SUB_F32X2(dz2, pzp[jp], cz2);
            MUL_F32X2(sx2, dx2, dx2);
            MUL_F32X2(sy2, dy2, dy2);
            MUL_F32X2(sz2, dz2, dz2);
            ADD_F32X2(s12, sx2, sy2);
            ADD_F32X2(s22, s12, sz2);
            float t0, t1;
            UNPACK_F32X2(t0, t1, s22);
            float n0 = fminf(dd[2*jp],     t0);
            float n1 = fminf(dd[2*jp + 1], t1);
            dd[2*jp]     = n0;
            dd[2*jp + 1] = n1;
            best = fmaxf(best, n0);
            best = fmaxf(best, n1);
        }

        unsigned bmax = __float_as_uint(best);
        unsigned wm;
        REDUX_MAX_U32(wm, bmax);
        if (lane == 0) swmax[wid] = wm;
        __syncthreads();                                    // barrier (a)

        if (tid == 32) sh_idx[(s + 1) & 1] = 0x7FFFFFFF;

        unsigned v = swmax[lane & 15];
        unsigned gmax;
        REDUX_MAX_U32(gmax, v);

        if (bmax == gmax) {
            int cand = 0x7FFFFFFF;
#pragma unroll
            for (int j = 15; j >= 0; j--)
                if (__float_as_uint(dd[j]) == gmax) cand = tid + 512 * j;
            atomicMin(&sh_idx[s & 1], cand);
        }
        __syncthreads();                                    // barrier (b)

        const int idx = sh_idx[s & 1];
        ce = spk[idx];

        if (tid == 96) sidx_s[s] = idx;
    }

    __syncthreads();
    for (int e = tid; e < SS; e += 512) {
        int idx = sidx_s[e];
        float4 v = spk[idx];
        g_sidx[b * SS + e] = idx;
        out[OFF_IDX + b * SS + e] = (float)idx;
        out[OFF_XYZ + (size_t)(b * 3 + 0) * SS + e] = v.x;
        out[OFF_XYZ + (size_t)(b * 3 + 1) * SS + e] = v.y;
        out[OFF_XYZ + (size_t)(b * 3 + 2) * SS + e] = v.z;
    }
}

// ============================================================================
// Kernel 2: gather sampled features (norms moved into the gemm).
// ============================================================================
__global__ void gather_kernel(const float* __restrict__ x)
{
    int t = blockIdx.x * blockDim.x + threadIdx.x;
    if (t >= BB * CC * SS) return;
    int m = t & (SS - 1);
    int c = (t >> 11) & 63;
    int b = t >> 17;
    int n = g_sidx[b * SS + m];
    g_sx[t] = x[((size_t)(b * CC + c)) * NN + n];
}

// ============================================================================
// Kernel 4: distance GEMM + in-block norms + per-(row,tile) min epilogue.
// qn/pn are recomputed per block from the smem tiles with the identical
// sequential __fadd_rn(acc, __fmul_rn(v,v)) chain over c = 0..63 (same
// values, same order as the former norms kernel -> bit-identical D).
// ============================================================================
__global__ __launch_bounds__(256) void knn_gemm_kernel(const float* __restrict__ x)
{
    extern __shared__ float sm[];
    float* Qs = sm;                // [64][128]
    float* Ps = sm + 64 * 128;     // [64][128]
    __shared__ float qn_s[128];
    __shared__ float pn_s[128];

    const int b  = blockIdx.z;
    const int mt = blockIdx.y;
    const int nt = blockIdx.x;
    const int tid = threadIdx.x;

    const float* qb = g_sx + (size_t)(b * CC) * SS + mt * 128;
    const float* pb = x    + (size_t)(b * CC) * NN + nt * 128;

    for (int e = tid; e < 64 * 32; e += 256) {
        int c = e >> 5, i = e & 31;
        ((float4*)(Qs + c * 128))[i] = ((const float4*)(qb + (size_t)c * SS))[i];
        ((float4*)(Ps + c * 128))[i] = ((const float4*)(pb + (size_t)c * NN))[i];
    }
    __syncthreads();

    // column norms from the tiles (exact sequential chain over c)
    {
        const float* src = (tid < 128) ? Qs : Ps;
        const int    col = tid & 127;
        float acc = 0.0f;
        for (int c = 0; c < CC; c++) {
            float v = src[c * 128 + col];
            acc = __fadd_rn(acc, __fmul_rn(v, v));
        }
        if (tid < 128) qn_s[col] = acc; else pn_s[col] = acc;
    }
    __syncthreads();

    const int tx = tid & 15, ty = tid >> 4;
    float acc[8][8];
#pragma unroll
    for (int i = 0; i < 8; i++)
#pragma unroll
        for (int j = 0; j < 8; j++) acc[i][j] = 0.0f;

#pragma unroll 8
    for (int j = 0; j < 64; j++) {
        float4 a0 = *(const float4*)(Qs + j * 128 + ty * 8);
        float4 a1 = *(const float4*)(Qs + j * 128 + ty * 8 + 4);
        float4 c0 = *(const float4*)(Ps + j * 128 + tx * 8);
        float4 c1 = *(const float4*)(Ps + j * 128 + tx * 8 + 4);
        float av[8] = {a0.x, a0.y, a0.z, a0.w, a1.x, a1.y, a1.z, a1.w};
        float bv[8] = {c0.x, c0.y, c0.z, c0.w, c1.x, c1.y, c1.z, c1.w};
#pragma unroll
        for (int i = 0; i < 8; i++)
#pragma unroll
            for (int jj = 0; jj < 8; jj++)
                acc[i][jj] = fmaf(av[i], bv[jj], acc[i][jj]);
    }

    const int m0 = mt * 128 + ty * 8;
    const int n0 = nt * 128 + tx * 8;
    float qnv[8], pnv[8];
#pragma unroll
    for (int i = 0; i < 8; i++) qnv[i] = qn_s[ty * 8 + i];
#pragma unroll
    for (int j = 0; j < 8; j++) pnv[j] = pn_s[tx * 8 + j];

#pragma unroll
    for (int i = 0; i < 8; i++) {
        float* Drow = g_D + ((size_t)(b * SS + m0 + i)) * NN + n0;
        float4 v0, v1;
        float t0 = __fadd_rn(qnv[i], pnv[0]); v0.x = t0 - 2.0f * acc[i][0];
        float t1 = __fadd_rn(qnv[i], pnv[1]); v0.y = t1 - 2.0f * acc[i][1];
        float t2 = __fadd_rn(qnv[i], pnv[2]); v0.z = t2 - 2.0f * acc[i][2];
        float t3 = __fadd_rn(qnv[i], pnv[3]); v0.w = t3 - 2.0f * acc[i][3];
        float t4 = __fadd_rn(qnv[i], pnv[4]); v1.x = t4 - 2.0f * acc[i][4];
        float t5 = __fadd_rn(qnv[i], pnv[5]); v1.y = t5 - 2.0f * acc[i][5];
        float t6 = __fadd_rn(qnv[i], pnv[6]); v1.z = t6 - 2.0f * acc[i][6];
        float t7 = __fadd_rn(qnv[i], pnv[7]); v1.w = t7 - 2.0f * acc[i][7];
        ((float4*)Drow)[0] = v0;
        ((float4*)Drow)[1] = v1;

        float mn = fminf(fminf(fminf(v0.x, v0.y), fminf(v0.z, v0.w)),
                         fminf(fminf(v1.x, v1.y), fminf(v1.z, v1.w)));
#pragma unroll
        for (int off = 8; off; off >>= 1)
            mn = fminf(mn, __shfl_xor_sync(0xFFFFFFFFu, mn, off));
        if (tx == 0)
            g_tmin[(b * SS + m0 + i) * 64 + nt] = mn;
    }
}

// ============================================================================
// Kernel 5: per-row top-17 via threshold filter + tile skip (R14, verbatim).
// ============================================================================
__device__ __forceinline__ unsigned ord_map(float f) {
    unsigned fb = __float_as_uint(f);
    return (fb & 0x80000000u) ? ~fb : (fb | 0x80000000u);
}

__global__ __launch_bounds__(256) void topk_kernel()
{
    __shared__ unsigned long long cand[8][256];
    const int w    = threadIdx.x >> 5;
    const int lane = threadIdx.x & 31;
    const int row  = blockIdx.x * 8 + w;

    const float4* dr4 = (const float4*)(g_D + (size_t)row * NN);

    const float tmin_lo = g_tmin[row * 64 + lane];
    const float tmin_hi = g_tmin[row * 64 + 32 + lane];
    float mn = fminf(tmin_lo, tmin_hi);

    float sv = mn;
#pragma unroll
    for (int k = 2; k <= 32; k <<= 1) {
#pragma unroll
        for (int j = k >> 1; j > 0; j >>= 1) {
            float other = __shfl_xor_sync(0xFFFFFFFFu, sv, j);
            bool up   = ((lane & k) == 0);
            bool smal = ((lane & j) == 0);
            sv = ((smal == up) ? fminf(sv, other) : fmaxf(sv, other));
        }
    }
    const float tau = __shfl_sync(0xFFFFFFFFu, sv, 17);

    const unsigned pm_lo = __ballot_sync(0xFFFFFFFFu, tmin_lo <= tau);
    const unsigned pm_hi = __ballot_sync(0xFFFFFFFFu, tmin_hi <= tau);

#pragma unroll
    for (int i = 0; i < 8; i++) cand[w][lane + (i << 5)] = ~0ULL;
    __syncwarp();

    unsigned cnt = 0;
    for (int t = 0; t < 64; t++) {
        bool tile_pass = (t < 32) ? ((pm_lo >> t) & 1u)
                                  : ((pm_hi >> (t - 32)) & 1u);
        if (!tile_pass) continue;               // warp-uniform
        float4 v = dr4[t * 32 + lane];
        const int nb = t * 128 + lane * 4;
        float el[4] = {v.x, v.y, v.z, v.w};
#pragma unroll
        for (int j = 0; j < 4; j++) {
            bool pass = (el[j] <= tau);
            unsigned m = __ballot_sync(0xFFFFFFFFu, pass);
            if (pass) {
                unsigned pos = cnt + __popc(m & ((1u << lane) - 1u));
                if (pos < 256)
                    cand[w][pos] = ((unsigned long long)ord_map(el[j]) << 32)
                                 | (unsigned)(nb + j);
            }
            cnt += __popc(m);
        }
    }
    __syncwarp();

    if (cnt <= 256) {
        const int slots = (int)((cnt + 31) >> 5);
        for (int r = 0; r < 17; r++) {
            unsigned long long mk = ~0ULL;
            int ms = 0;
            for (int q = 0; q < slots; q++) {
                unsigned long long vq = cand[w][lane + (q << 5)];
                if (vq < mk) { mk = vq; ms = lane + (q << 5); }
            }
            unsigned long long gk = mk;
#pragma unroll
            for (int off = 16; off; off >>= 1) {
                unsigned long long o = __shfl_xor_sync(0xFFFFFFFFu, gk, off);
                if (o < gk) gk = o;
            }
            if (gk == mk) cand[w][ms] = ~0ULL;
            if (r > 0 && lane == 0)
                g_knn[row * KNBR + r - 1] = (int)(gk & (unsigned long long)(NN - 1));
            __syncwarp();
        }
    } else {
        unsigned long long last = 0;
        for (int r = 0; r < 17; r++) {
            unsigned long long mk = ~0ULL;
            for (int t = 0; t < 64; t++) {
                float4 v = dr4[lane + (t << 5)];
                const int nb = 4 * (lane + (t << 5));
                float el[4] = {v.x, v.y, v.z, v.w};
#pragma unroll
                for (int j = 0; j < 4; j++) {
                    unsigned long long key =
                        ((unsigned long long)ord_map(el[j]) << 32)
                        | (unsigned)(nb + j);
                    if (key >= last && key < mk) mk = key;
                }
            }
            unsigned long long gk = mk;
#pragma unroll
            for (int off = 16; off; off >>= 1) {
                unsigned long long o = __shfl_xor_sync(0xFFFFFFFFu, gk, off);
                if (o < gk) gk = o;
            }
            if (r > 0 && lane == 0)
                g_knn[row * KNBR + r - 1] = (int)(gk & (unsigned long long)(NN - 1));
            last = gk + 1;
        }
    }
}

// ============================================================================
// Kernel 6: fused EdgeConv + max-pool. 16 samples/block (fixed cost amortized)
// but 512 threads (16 warps hide LDS/barrier latency on the single-resident
// CTA). Per-element arithmetic identical to the 256-thread version; only the
// thread->work mapping changes (4x8 microtile instead of 8x8).
// ============================================================================
__device__ __forceinline__ void load_wt(const float* __restrict__ W, int RL, int CO,
                                        float* __restrict__ dst, int tid)
{
    for (int e = tid; e < 4096; e += 512) {
        int j = e >> 6, o = e & 63;
        dst[j * 64 + o] = W[o * RL + CO + j];
    }
}

__device__ __forceinline__ void compute_u(const float* __restrict__ W, int RL, int CO,
                                          const float* __restrict__ bias,
                                          const float* __restrict__ sC,
                                          float* __restrict__ sU, int tid)
{
    const int o = tid & 63, g = tid >> 6;     // g in 0..7, 2 ml per thread
    float a[2] = {0.f, 0.f};
    for (int j = 0; j < 64; j++) {
        float w = W[o * RL + CO + j];
#pragma unroll
        for (int i = 0; i < 2; i++)
            a[i] = fmaf(w, sC[j * 16 + g * 2 + i], a[i]);
    }
    float bv = bias[o];
#pragma unroll
    for (int i = 0; i < 2; i++) sU[o * 16 + g * 2 + i] = a[i] + bv;
}

__device__ __forceinline__ void gemm_stage(const float* __restrict__ sWt,
                                           const float* __restrict__ sIn,
                                           const float* __restrict__ sU,
                                           float* __restrict__ sOut, int tid)
{
    const int tx = tid & 31, ty = tid >> 5;   // ty in 0..15
    const int col0 = tx * 8, o0 = ty * 4;
    float acc[4][8];
#pragma unroll
    for (int i = 0; i < 4; i++)
#pragma unroll
        for (int j = 0; j < 8; j++) acc[i][j] = 0.0f;

#pragma unroll 4
    for (int j = 0; j < 64; j++) {
        float4 w0 = *(const float4*)(sWt + j * 64 + o0);
        float4 e0 = *(const float4*)(sIn + j * 256 + col0);
        float4 e1 = *(const float4*)(sIn + j * 256 + col0 + 4);
        float wv[4] = {w0.x, w0.y, w0.z, w0.w};
        float ev[8] = {e0.x, e0.y, e0.z, e0.w, e1.x, e1.y, e1.z, e1.w};
#pragma unroll
        for (int i = 0; i < 4; i++)
#pragma unroll
            for (int jj = 0; jj < 8; jj++)
                acc[i][jj] = fmaf(wv[i], ev[jj], acc[i][jj]);
    }
    const int ml = tx >> 1;
#pragma unroll
    for (int i = 0; i < 4; i++) {
        float u = sU[(o0 + i) * 16 + ml];
#pragma unroll
        for (int jj = 0; jj < 8; jj++) {
            float v = acc[i][jj] + u;
            sOut[(o0 + i) * 256 + col0 + jj] = fmaxf(v, 0.0f);
        }
    }
}

__global__ __launch_bounds__(512) void edge_kernel(
    const float* __restrict__ x,
    const float* __restrict__ W0, const float* __restrict__ b0,
    const float* __restrict__ W1, const float* __restrict__ b1,
    const float* __restrict__ W2, const float* __restrict__ b2,
    float* __restrict__ out)
{
    extern __shared__ float sm[];
    float* sE  = sm;                  // [64][256]  -> later reused as H1
    float* sH0 = sE  + 64 * 256;      // [64][256]
    float* sWa = sH0 + 64 * 256;      // [64][64]
    float* sWb = sWa + 64 * 64;       // [64][64]
    float* sC  = sWb + 64 * 64;       // [64][16]
    float* sU  = sC  + 64 * 16;       // [64][16]

    const int blk = blockIdx.x;
    const int b   = blk >> 7;
    const int m0  = (blk & 127) * 16;
    const int tid = threadIdx.x;

    for (int e = tid; e < 1024; e += 512) {
        int c = e >> 4, ml = e & 15;
        sC[e] = g_sx[((size_t)(b * CC + c)) * SS + m0 + ml];
    }
    __syncthreads();

    // E = knn_feat - center: 256 cols, 2 threads per col (half channels each)
    {
        const int col  = tid & 255;
        const int half = tid >> 8;              // 0 or 1
        const int ml = col >> 4, kk = col & 15;
        const int n = g_knn[(b * SS + m0 + ml) * KNBR + kk];
        const float* xb = x + (size_t)(b * CC) * NN + n;
#pragma unroll 8
        for (int c = half * 32; c < half * 32 + 32; c++)
            sE[c * 256 + col] = xb[(size_t)c * NN] - sC[c * 16 + ml];
    }
    load_wt(W0, 128, 64, sWa, tid);
    compute_u(W0, 128, 0, b0, sC, sU, tid);
    __syncthreads();

    gemm_stage(sWa, sE, sU, sH0, tid);
    __syncthreads();

    load_wt(W1, 128, 0, sWa, tid);
    compute_u(W1, 128, 64, b1, sC, sU, tid);
    __syncthreads();

    gemm_stage(sWa, sH0, sU, sE, tid);
    __syncthreads();
    float* sH1 = sE;

    load_wt(W2, 192, 0,  sWa, tid);
    load_wt(W2, 192, 64, sWb, tid);
    compute_u(W2, 192, 128, b2, sC, sU, tid);
    __syncthreads();

    // stage 2: h2 = W2a@H1 + W2b@H0 + V2 (no relu), max over k
    {
        const int tx = tid & 31, ty = tid >> 5;
        const int col0 = tx * 8, o0 = ty * 4;
        float acc[4][8];
#pragma unroll
        for (int i = 0; i < 4; i++)
#pragma unroll
            for (int j = 0; j < 8; j++) acc[i][j] = 0.0f;

#pragma unroll 2
        for (int j = 0; j < 64; j++) {
            float4 w0 = *(const float4*)(sWa + j * 64 + o0);
            float4 u0 = *(const float4*)(sWb + j * 64 + o0);
            float4 h1a = *(const float4*)(sH1 + j * 256 + col0);
            float4 h1b = *(const float4*)(sH1 + j * 256 + col0 + 4);
            float4 h0a = *(const float4*)(sH0 + j * 256 + col0);
            float4 h0b = *(const float4*)(sH0 + j * 256 + col0 + 4);
            float wv[4]  = {w0.x, w0.y, w0.z, w0.w};
            float w2v[4] = {u0.x, u0.y, u0.z, u0.w};
            float v1v[8] = {h1a.x, h1a.y, h1a.z, h1a.w, h1b.x, h1b.y, h1b.z, h1b.w};
            float v0v[8] = {h0a.x, h0a.y, h0a.z, h0a.w, h0b.x, h0b.y, h0b.z, h0b.w};
#pragma unroll
            for (int i = 0; i < 4; i++)
#pragma unroll
                for (int jj = 0; jj < 8; jj++) {
                    acc[i][jj] = fmaf(wv[i],  v1v[jj], acc[i][jj]);
                    acc[i][jj] = fmaf(w2v[i], v0v[jj], acc[i][jj]);
                }
        }
        const int ml = tx >> 1;
#pragma unroll
        for (int i = 0; i < 4; i++) {
            float mx = acc[i][0];
#pragma unroll
            for (int jj = 1; jj < 8; jj++) mx = fmaxf(mx, acc[i][jj]);
            mx = mx + sU[(o0 + i) * 16 + ml];
            float other = __shfl_xor_sync(0xFFFFFFFFu, mx, 1);
            mx = fmaxf(mx, other);
            if ((tx & 1) == 0)
                out[(size_t)(b * 256 + o0 + i) * SS + m0 + ml] = mx;   // ch 0..63
        }
    }

    for (int e = tid; e < 1024; e += 512) {
        int ch = e >> 4, ml = e & 15;
        float mx0 = -__int_as_float(0x7F7FFFFF);
        float mx1 = mx0;
#pragma unroll
        for (int kk = 0; kk < 16; kk++) {
            mx0 = fmaxf(mx0, sH0[ch * 256 + ml * 16 + kk]);
            mx1 = fmaxf(mx1, sH1[ch * 256 + ml * 16 + kk]);
        }
        size_t base = (size_t)b * 256;
        out[(base + 64  + ch) * SS + m0 + ml] = mx1;            // ch 64..127
        out[(base + 128 + ch) * SS + m0 + ml] = mx0;            // ch 128..191
        out[(base + 192 + ch) * SS + m0 + ml] = sC[ch * 16 + ml]; // ch 192..255
    }
}

// ============================================================================
extern "C" void kernel_launch(void* const* d_in, const int* in_sizes, int n_in,
                              void* d_out, int out_size)
{
    const float* x   = (const float*)d_in[0];
    const float* xyz = (const float*)d_in[1];
    const float* W0  = (const float*)d_in[2];
    const float* b0  = (const float*)d_in[3];
    const float* W1  = (const float*)d_in[4];
    const float* b1  = (const float*)d_in[5];
    const float* W2  = (const float*)d_in[6];
    const float* b2  = (const float*)d_in[7];
    float* out = (float*)d_out;

    cudaFuncSetAttribute(fps_kernel,
                         cudaFuncAttributeMaxDynamicSharedMemorySize, 131072);
    cudaFuncSetAttribute(knn_gemm_kernel,
                         cudaFuncAttributeMaxDynamicSharedMemorySize, 65536);
    cudaFuncSetAttribute(edge_kernel,
                         cudaFuncAttributeMaxDynamicSharedMemorySize, 172032);

    fps_kernel<<<BB, 512, 131072>>>(xyz, out);
    gather_kernel<<<(BB * CC * SS + 255) / 256, 256>>>(x);
    knn_gemm_kernel<<<dim3(NN / 128, SS / 128, BB), 256, 65536>>>(x);
    topk_kernel<<<BB * SS / 8, 256>>>();
    edge_kernel<<<BB * SS / 16, 512, 172032>>>(x, W0, b0, W1, b1, W2, b2, out);
}

// round 16
// speedup vs baseline: 1.0931x; 1.0931x over previous
#include <cuda_runtime.h>

#define BB 4
#define CC 64
#define NN 8192
#define SS 2048
#define KNBR 16
#define GG 64

#define OFF_XYZ (4*256*2048)            /* 2097152 */
#define OFF_IDX (OFF_XYZ + 4*3*2048)    /* 2121728 */

#define MUL_F32X2(out, a, b) \
    asm("mul.rn.f32x2 %0, %1, %2;" : "=l"(out) : "l"(a), "l"(b))
#define ADD_F32X2(out, a, b) \
    asm("add.rn.f32x2 %0, %1, %2;" : "=l"(out) : "l"(a), "l"(b))
#define SUB_F32X2(out, a, b) \
    asm("sub.rn.f32x2 %0, %1, %2;" : "=l"(out) : "l"(a), "l"(b))
#define PACK_F32X2(out, lo, hi) \
    asm("mov.b64 %0, {%1, %2};" : "=l"(out) : "f"(lo), "f"(hi))
#define UNPACK_F32X2(lo, hi, in) \
    asm("mov.b64 {%0, %1}, %2;" : "=f"(lo), "=f"(hi) : "l"(in))
#define REDUX_MAX_U32(d, s) \
    asm volatile("redux.sync.max.u32 %0, %1, 0xffffffff;" : "=r"(d) : "r"(s))

// ---------------- scratch (static device globals; no allocations) ----------
__device__ int   g_sidx[BB*SS];
__device__ float g_sx[BB*CC*SS];
__device__ float g_D[(size_t)BB*SS*NN];    // 256 MB distance matrix
__device__ float g_tmin[BB*SS*64];         // per-(row, 128-col tile) min (2 MB)
__device__ int   g_knn[BB*SS*KNBR];

// ============================================================================
// Kernel 1: Farthest point sampling (R12/R14 winner, verbatim). Bit-exact.
// ============================================================================
__global__ __launch_bounds__(512) void fps_kernel(const float* __restrict__ xyz,
                                                  float* __restrict__ out)
{
    extern __shared__ float4 spk[];               // [8192] packed {x,y,z,0}

    const int b    = blockIdx.x;
    const int tid  = threadIdx.x;
    const int lane = tid & 31;
    const int wid  = tid >> 5;
    const float* xb = xyz + (size_t)b * 3 * NN;

    __shared__ unsigned swmax[16];
    __shared__ int      sh_idx[2];
    __shared__ int      sidx_s[SS];               // winner log

#pragma unroll
    for (int k = 0; k < 16; k++) {
        int i = tid + 512 * k;
        float4 v;
        v.x = xb[i];
        v.y = xb[NN + i];
        v.z = xb[2*NN + i];
        v.w = 0.0f;
        spk[i] = v;
    }

    unsigned long long pxp[8], pyp[8], pzp[8];
    float dd[16];
    const float FMAX = __int_as_float(0x7F7FFFFF);
#pragma unroll
    for (int jp = 0; jp < 8; jp++) {
        int n0 = tid + 1024 * jp;
        int n1 = n0 + 512;
        PACK_F32X2(pxp[jp], xb[n0],          xb[n1]);
        PACK_F32X2(pyp[jp], xb[NN + n0],     xb[NN + n1]);
        PACK_F32X2(pzp[jp], xb[2*NN + n0],   xb[2*NN + n1]);
        dd[2*jp]     = FMAX;
        dd[2*jp + 1] = FMAX;
    }

    if (tid == 0) {
        sh_idx[0] = 0x7FFFFFFF;
        sh_idx[1] = 0x7FFFFFFF;
        sidx_s[0] = 0;
    }
    __syncthreads();

    float4 ce = spk[0];

    for (int s = 1; s < SS; s++) {
        unsigned long long cx2, cy2, cz2;
        PACK_F32X2(cx2, ce.x, ce.x);
        PACK_F32X2(cy2, ce.y, ce.y);
        PACK_F32X2(cz2, ce.z, ce.z);

        float best = 0.0f;
#pragma unroll
        for (int jp = 0; jp < 8; jp++) {
            unsigned long long dx2, dy2, dz2, sx2, sy2, sz2, s12, s22;
            SUB_F32X2(dx2, pxp[jp], cx2);
            SUB_F32X2(dy2, pyp[jp], cy2);
            SUB_F32X2(dz2, pzp[jp], cz2);
            MUL_F32X2(sx2, dx2, dx2);
            MUL_F32X2(sy2, dy2, dy2);
            MUL_F32X2(sz2, dz2, dz2);
            ADD_F32X2(s12, sx2, sy2);
            ADD_F32X2(s22, s12, sz2);
            float t0, t1;
            UNPACK_F32X2(t0, t1, s22);
            float n0 = fminf(dd[2*jp],     t0);
            float n1 = fminf(dd[2*jp + 1], t1);
            dd[2*jp]     = n0;
            dd[2*jp + 1] = n1;
            best = fmaxf(best, n0);
            best = fmaxf(best, n1);
        }

        unsigned bmax = __float_as_uint(best);
        unsigned wm;
        REDUX_MAX_U32(wm, bmax);
        if (lane == 0) swmax[wid] = wm;
        __syncthreads();                                    // barrier (a)

        if (tid == 32) sh_idx[(s + 1) & 1] = 0x7FFFFFFF;

        unsigned v = swmax[lane & 15];
        unsigned gmax;
        REDUX_MAX_U32(gmax, v);

        if (bmax == gmax) {
            int cand = 0x7FFFFFFF;
#pragma unroll
            for (int j = 15; j >= 0; j--)
                if (__float_as_uint(dd[j]) == gmax) cand = tid + 512 * j;
            atomicMin(&sh_idx[s & 1], cand);
        }
        __syncthreads();                                    // barrier (b)

        const int idx = sh_idx[s & 1];
        ce = spk[idx];

        if (tid == 96) sidx_s[s] = idx;
    }

    __syncthreads();
    for (int e = tid; e < SS; e += 512) {
        int idx = sidx_s[e];
        float4 v = spk[idx];
        g_sidx[b * SS + e] = idx;
        out[OFF_IDX + b * SS + e] = (float)idx;
        out[OFF_XYZ + (size_t)(b * 3 + 0) * SS + e] = v.x;
        out[OFF_XYZ + (size_t)(b * 3 + 1) * SS + e] = v.y;
        out[OFF_XYZ + (size_t)(b * 3 + 2) * SS + e] = v.z;
    }
}

// ============================================================================
// Kernel 2: gather sampled features (norms computed inside the gemm).
// ============================================================================
__global__ void gather_kernel(const float* __restrict__ x)
{
    int t = blockIdx.x * blockDim.x + threadIdx.x;
    if (t >= BB * CC * SS) return;
    int m = t & (SS - 1);
    int c = (t >> 11) & 63;
    int b = t >> 17;
    int n = g_sidx[b * SS + m];
    g_sx[t] = x[((size_t)(b * CC + c)) * NN + n];
}

// ============================================================================
// Kernel 4: distance GEMM + in-block norms + per-(row,tile) min epilogue.
// qn/pn are recomputed per block from the smem tiles with the identical
// sequential __fadd_rn(acc, __fmul_rn(v,v)) chain over c = 0..63 (same
// values, same order as the former norms kernel -> bit-identical D).
// ============================================================================
__global__ __launch_bounds__(256) void knn_gemm_kernel(const float* __restrict__ x)
{
    extern __shared__ float sm[];
    float* Qs = sm;                // [64][128]
    float* Ps = sm + 64 * 128;     // [64][128]
    __shared__ float qn_s[128];
    __shared__ float pn_s[128];

    const int b  = blockIdx.z;
    const int mt = blockIdx.y;
    const int nt = blockIdx.x;
    const int tid = threadIdx.x;

    const float* qb = g_sx + (size_t)(b * CC) * SS + mt * 128;
    const float* pb = x    + (size_t)(b * CC) * NN + nt * 128;

    for (int e = tid; e < 64 * 32; e += 256) {
        int c = e >> 5, i = e & 31;
        ((float4*)(Qs + c * 128))[i] = ((const float4*)(qb + (size_t)c * SS))[i];
        ((float4*)(Ps + c * 128))[i] = ((const float4*)(pb + (size_t)c * NN))[i];
    }
    __syncthreads();

    // column norms from the tiles (exact sequential chain over c)
    {
        const float* src = (tid < 128) ? Qs : Ps;
        const int    col = tid & 127;
        float acc = 0.0f;
        for (int c = 0; c < CC; c++) {
            float v = src[c * 128 + col];
            acc = __fadd_rn(acc, __fmul_rn(v, v));
        }
        if (tid < 128) qn_s[col] = acc; else pn_s[col] = acc;
    }
    __syncthreads();

    const int tx = tid & 15, ty = tid >> 4;
    float acc[8][8];
#pragma unroll
    for (int i = 0; i < 8; i++)
#pragma unroll
        for (int j = 0; j < 8; j++) acc[i][j] = 0.0f;

#pragma unroll 8
    for (int j = 0; j < 64; j++) {
        float4 a0 = *(const float4*)(Qs + j * 128 + ty * 8);
        float4 a1 = *(const float4*)(Qs + j * 128 + ty * 8 + 4);
        float4 c0 = *(const float4*)(Ps + j * 128 + tx * 8);
        float4 c1 = *(const float4*)(Ps + j * 128 + tx * 8 + 4);
        float av[8] = {a0.x, a0.y, a0.z, a0.w, a1.x, a1.y, a1.z, a1.w};
        float bv[8] = {c0.x, c0.y, c0.z, c0.w, c1.x, c1.y, c1.z, c1.w};
#pragma unroll
        for (int i = 0; i < 8; i++)
#pragma unroll
            for (int jj = 0; jj < 8; jj++)
                acc[i][jj] = fmaf(av[i], bv[jj], acc[i][jj]);
    }

    const int m0 = mt * 128 + ty * 8;
    const int n0 = nt * 128 + tx * 8;
    float qnv[8], pnv[8];
#pragma unroll
    for (int i = 0; i < 8; i++) qnv[i] = qn_s[ty * 8 + i];
#pragma unroll
    for (int j = 0; j < 8; j++) pnv[j] = pn_s[tx * 8 + j];

#pragma unroll
    for (int i = 0; i < 8; i++) {
        float* Drow = g_D + ((size_t)(b * SS + m0 + i)) * NN + n0;
        float4 v0, v1;
        float t0 = __fadd_rn(qnv[i], pnv[0]); v0.x = t0 - 2.0f * acc[i][0];
        float t1 = __fadd_rn(qnv[i], pnv[1]); v0.y = t1 - 2.0f * acc[i][1];
        float t2 = __fadd_rn(qnv[i], pnv[2]); v0.z = t2 - 2.0f * acc[i][2];
        float t3 = __fadd_rn(qnv[i], pnv[3]); v0.w = t3 - 2.0f * acc[i][3];
        float t4 = __fadd_rn(qnv[i], pnv[4]); v1.x = t4 - 2.0f * acc[i][4];
        float t5 = __fadd_rn(qnv[i], pnv[5]); v1.y = t5 - 2.0f * acc[i][5];
        float t6 = __fadd_rn(qnv[i], pnv[6]); v1.z = t6 - 2.0f * acc[i][6];
        float t7 = __fadd_rn(qnv[i], pnv[7]); v1.w = t7 - 2.0f * acc[i][7];
        ((float4*)Drow)[0] = v0;
        ((float4*)Drow)[1] = v1;

        float mn = fminf(fminf(fminf(v0.x, v0.y), fminf(v0.z, v0.w)),
                         fminf(fminf(v1.x, v1.y), fminf(v1.z, v1.w)));
#pragma unroll
        for (int off = 8; off; off >>= 1)
            mn = fminf(mn, __shfl_xor_sync(0xFFFFFFFFu, mn, off));
        if (tx == 0)
            g_tmin[(b * SS + m0 + i) * 64 + nt] = mn;
    }
}

// ============================================================================
// Kernel 5: per-row top-17 via threshold filter + tile skip (R14, verbatim).
// ============================================================================
__device__ __forceinline__ unsigned ord_map(float f) {
    unsigned fb = __float_as_uint(f);
    return (fb & 0x80000000u) ? ~fb : (fb | 0x80000000u);
}

__global__ __launch_bounds__(256) void topk_kernel()
{
    __shared__ unsigned long long cand[8][256];
    const int w    = threadIdx.x >> 5;
    const int lane = threadIdx.x & 31;
    const int row  = blockIdx.x * 8 + w;

    const float4* dr4 = (const float4*)(g_D + (size_t)row * NN);

    const float tmin_lo = g_tmin[row * 64 + lane];
    const float tmin_hi = g_tmin[row * 64 + 32 + lane];
    float mn = fminf(tmin_lo, tmin_hi);

    float sv = mn;
#pragma unroll
    for (int k = 2; k <= 32; k <<= 1) {
#pragma unroll
        for (int j = k >> 1; j > 0; j >>= 1) {
            float other = __shfl_xor_sync(0xFFFFFFFFu, sv, j);
            bool up   = ((lane & k) == 0);
            bool smal = ((lane & j) == 0);
            sv = ((smal == up) ? fminf(sv, other) : fmaxf(sv, other));
        }
    }
    const float tau = __shfl_sync(0xFFFFFFFFu, sv, 17);

    const unsigned pm_lo = __ballot_sync(0xFFFFFFFFu, tmin_lo <= tau);
    const unsigned pm_hi = __ballot_sync(0xFFFFFFFFu, tmin_hi <= tau);

#pragma unroll
    for (int i = 0; i < 8; i++) cand[w][lane + (i << 5)] = ~0ULL;
    __syncwarp();

    unsigned cnt = 0;
    for (int t = 0; t < 64; t++) {
        bool tile_pass = (t < 32) ? ((pm_lo >> t) & 1u)
                                  : ((pm_hi >> (t - 32)) & 1u);
        if (!tile_pass) continue;               // warp-uniform
        float4 v = dr4[t * 32 + lane];
        const int nb = t * 128 + lane * 4;
        float el[4] = {v.x, v.y, v.z, v.w};
#pragma unroll
        for (int j = 0; j < 4; j++) {
            bool pass = (el[j] <= tau);
            unsigned m = __ballot_sync(0xFFFFFFFFu, pass);
            if (pass) {
                unsigned pos = cnt + __popc(m & ((1u << lane) - 1u));
                if (pos < 256)
                    cand[w][pos] = ((unsigned long long)ord_map(el[j]) << 32)
                                 | (unsigned)(nb + j);
            }
            cnt += __popc(m);
        }
    }
    __syncwarp();

    if (cnt <= 256) {
        const int slots = (int)((cnt + 31) >> 5);
        for (int r = 0; r < 17; r++) {
            unsigned long long mk = ~0ULL;
            int ms = 0;
            for (int q = 0; q < slots; q++) {
                unsigned long long vq = cand[w][lane + (q << 5)];
                if (vq < mk) { mk = vq; ms = lane + (q << 5); }
            }
            unsigned long long gk = mk;
#pragma unroll
            for (int off = 16; off; off >>= 1) {
                unsigned long long o = __shfl_xor_sync(0xFFFFFFFFu, gk, off);
                if (o < gk) gk = o;
            }
            if (gk == mk) cand[w][ms] = ~0ULL;
            if (r > 0 && lane == 0)
                g_knn[row * KNBR + r - 1] = (int)(gk & (unsigned long long)(NN - 1));
            __syncwarp();
        }
    } else {
        unsigned long long last = 0;
        for (int r = 0; r < 17; r++) {
            unsigned long long mk = ~0ULL;
            for (int t = 0; t < 64; t++) {
                float4 v = dr4[lane + (t << 5)];
                const int nb = 4 * (lane + (t << 5));
                float el[4] = {v.x, v.y, v.z, v.w};
#pragma unroll
                for (int j = 0; j < 4; j++) {
                    unsigned long long key =
                        ((unsigned long long)ord_map(el[j]) << 32)
                        | (unsigned)(nb + j);
                    if (key >= last && key < mk) mk = key;
                }
            }
            unsigned long long gk = mk;
#pragma unroll
            for (int off = 16; off; off >>= 1) {
                unsigned long long o = __shfl_xor_sync(0xFFFFFFFFu, gk, off);
                if (o < gk) gk = o;
            }
            if (r > 0 && lane == 0)
                g_knn[row * KNBR + r - 1] = (int)(gk & (unsigned long long)(NN - 1));
            last = gk + 1;
        }
    }
}

// ============================================================================
// Kernel 6: fused EdgeConv + max-pool (R12/R14 winner, verbatim: 16 samples
// per block, 256 threads, 8x8 microtiles).
// ============================================================================
__device__ __forceinline__ void load_wt(const float* __restrict__ W, int RL, int CO,
                                        float* __restrict__ dst, int tid)
{
    for (int e = tid; e < 4096; e += 256) {
        int j = e >> 6, o = e & 63;
        dst[j * 64 + o] = W[o * RL + CO + j];
    }
}

__device__ __forceinline__ void compute_u(const float* __restrict__ W, int RL, int CO,
                                          const float* __restrict__ bias,
                                          const float* __restrict__ sC,
                                          float* __restrict__ sU, int tid)
{
    const int o = tid & 63, g = tid >> 6;
    float a[4] = {0.f, 0.f, 0.f, 0.f};
    for (int j = 0; j < 64; j++) {
        float w = W[o * RL + CO + j];
#pragma unroll
        for (int i = 0; i < 4; i++)
            a[i] = fmaf(w, sC[j * 16 + g * 4 + i], a[i]);
    }
    float bv = bias[o];
#pragma unroll
    for (int i = 0; i < 4; i++) sU[o * 16 + g * 4 + i] = a[i] + bv;
}

__device__ __forceinline__ void gemm_stage(const float* __restrict__ sWt,
                                           const float* __restrict__ sIn,
                                           const float* __restrict__ sU,
                                           float* __restrict__ sOut, int tid)
{
    const int tx = tid & 31, ty = tid >> 5;
    const int col0 = tx * 8, o0 = ty * 8;
    float acc[8][8];
#pragma unroll
    for (int i = 0; i < 8; i++)
#pragma unroll
        for (int j = 0; j < 8; j++) acc[i][j] = 0.0f;

#pragma unroll 4
    for (int j = 0; j < 64; j++) {
        float4 w0 = *(const float4*)(sWt + j * 64 + o0);
        float4 w1 = *(const float4*)(sWt + j * 64 + o0 + 4);
        float4 e0 = *(const float4*)(sIn + j * 256 + col0);
        float4 e1 = *(const float4*)(sIn + j * 256 + col0 + 4);
        float wv[8] = {w0.x, w0.y, w0.z, w0.w, w1.x, w1.y, w1.z, w1.w};
        float ev[8] = {e0.x, e0.y, e0.z, e0.w, e1.x, e1.y, e1.z, e1.w};
#pragma unroll
        for (int i = 0; i < 8; i++)
#pragma unroll
            for (int jj = 0; jj < 8; jj++)
                acc[i][jj] = fmaf(wv[i], ev[jj], acc[i][jj]);
    }
    const int ml = tx >> 1;
#pragma unroll
    for (int i = 0; i < 8; i++) {
        float u = sU[(o0 + i) * 16 + ml];
#pragma unroll
        for (int jj = 0; jj < 8; jj++) {
            float v = acc[i][jj] + u;
            sOut[(o0 + i) * 256 + col0 + jj] = fmaxf(v, 0.0f);
        }
    }
}

__global__ __launch_bounds__(256) void edge_kernel(
    const float* __restrict__ x,
    const float* __restrict__ W0, const float* __restrict__ b0,
    const float* __restrict__ W1, const float* __restrict__ b1,
    const float* __restrict__ W2, const float* __restrict__ b2,
    float* __restrict__ out)
{
    extern __shared__ float sm[];
    float* sE  = sm;                  // [64][256]  -> later reused as H1
    float* sH0 = sE  + 64 * 256;      // [64][256]
    float* sWa = sH0 + 64 * 256;      // [64][64]
    float* sWb = sWa + 64 * 64;       // [64][64]
    float* sC  = sWb + 64 * 64;       // [64][16]
    float* sU  = sC  + 64 * 16;       // [64][16]

    const int blk = blockIdx.x;
    const int b   = blk >> 7;
    const int m0  = (blk & 127) * 16;
    const int tid = threadIdx.x;

    for (int e = tid; e < 1024; e += 256) {
        int c = e >> 4, ml = e & 15;
        sC[e] = g_sx[((size_t)(b * CC + c)) * SS + m0 + ml];
    }
    __syncthreads();

    {
        const int col = tid;
        const int ml = col >> 4, kk = col & 15;
        const int n = g_knn[(b * SS + m0 + ml) * KNBR + kk];
        const float* xb = x + (size_t)(b * CC) * NN + n;
#pragma unroll 8
        for (int c = 0; c < CC; c++)
            sE[c * 256 + col] = xb[(size_t)c * NN] - sC[c * 16 + ml];
    }
    load_wt(W0, 128, 64, sWa, tid);
    compute_u(W0, 128, 0, b0, sC, sU, tid);
    __syncthreads();

    gemm_stage(sWa, sE, sU, sH0, tid);
    __syncthreads();

    load_wt(W1, 128, 0, sWa, tid);
    compute_u(W1, 128, 64, b1, sC, sU, tid);
    __syncthreads();

    gemm_stage(sWa, sH0, sU, sE, tid);
    __syncthreads();
    float* sH1 = sE;

    load_wt(W2, 192, 0,  sWa, tid);
    load_wt(W2, 192, 64, sWb, tid);
    compute_u(W2, 192, 128, b2, sC, sU, tid);
    __syncthreads();

    {
        const int tx = tid & 31, ty = tid >> 5;
        const int col0 = tx * 8, o0 = ty * 8;
        float acc[8][8];
#pragma unroll
        for (int i = 0; i < 8; i++)
#pragma unroll
            for (int j = 0; j < 8; j++) acc[i][j] = 0.0f;

#pragma unroll 2
        for (int j = 0; j < 64; j++) {
            float4 w0 = *(const float4*)(sWa + j * 64 + o0);
            float4 w1 = *(const float4*)(sWa + j * 64 + o0 + 4);
            float4 u0 = *(const float4*)(sWb + j * 64 + o0);
            float4 u1 = *(const float4*)(sWb + j * 64 + o0 + 4);
            float4 h1a = *(const float4*)(sH1 + j * 256 + col0);
            float4 h1b = *(const float4*)(sH1 + j * 256 + col0 + 4);
            float4 h0a = *(const float4*)(sH0 + j * 256 + col0);
            float4 h0b = *(const float4*)(sH0 + j * 256 + col0 + 4);
            float wv[8]  = {w0.x, w0.y, w0.z, w0.w, w1.x, w1.y, w1.z, w1.w};
            float w2v[8] = {u0.x, u0.y, u0.z, u0.w, u1.x, u1.y, u1.z, u1.w};
            float v1v[8] = {h1a.x, h1a.y, h1a.z, h1a.w, h1b.x, h1b.y, h1b.z, h1b.w};
            float v0v[8] = {h0a.x, h0a.y, h0a.z, h0a.w, h0b.x, h0b.y, h0b.z, h0b.w};
#pragma unroll
            for (int i = 0; i < 8; i++)
#pragma unroll
                for (int jj = 0; jj < 8; jj++) {
                    acc[i][jj] = fmaf(wv[i],  v1v[jj], acc[i][jj]);
                    acc[i][jj] = fmaf(w2v[i], v0v[jj], acc[i][jj]);
                }
        }
        const int ml = tx >> 1;
#pragma unroll
        for (int i = 0; i < 8; i++) {
            float mx = acc[i][0];
#pragma unroll
            for (int jj = 1; jj < 8; jj++) mx = fmaxf(mx, acc[i][jj]);
            mx = mx + sU[(o0 + i) * 16 + ml];
            float other = __shfl_xor_sync(0xFFFFFFFFu, mx, 1);
            mx = fmaxf(mx, other);
            if ((tx & 1) == 0)
                out[(size_t)(b * 256 + o0 + i) * SS + m0 + ml] = mx;
        }
    }

    for (int e = tid; e < 1024; e += 256) {
        int ch = e >> 4, ml = e & 15;
        float mx0 = -__int_as_float(0x7F7FFFFF);
        float mx1 = mx0;
#pragma unroll
        for (int kk = 0; kk < 16; kk++) {
            mx0 = fmaxf(mx0, sH0[ch * 256 + ml * 16 + kk]);
            mx1 = fmaxf(mx1, sH1[ch * 256 + ml * 16 + kk]);
        }
        size_t base = (size_t)b * 256;
        out[(base + 64  + ch) * SS + m0 + ml] = mx1;
        out[(base + 128 + ch) * SS + m0 + ml] = mx0;
        out[(base + 192 + ch) * SS + m0 + ml] = sC[ch * 16 + ml];
    }
}

// ============================================================================
extern "C" void kernel_launch(void* const* d_in, const int* in_sizes, int n_in,
                              void* d_out, int out_size)
{
    const float* x   = (const float*)d_in[0];
    const float* xyz = (const float*)d_in[1];
    const float* W0  = (const float*)d_in[2];
    const float* b0  = (const float*)d_in[3];
    const float* W1  = (const float*)d_in[4];
    const float* b1  = (const float*)d_in[5];
    const float* W2  = (const float*)d_in[6];
    const float* b2  = (const float*)d_in[7];
    float* out = (float*)d_out;

    cudaFuncSetAttribute(fps_kernel,
                         cudaFuncAttributeMaxDynamicSharedMemorySize, 131072);
    cudaFuncSetAttribute(knn_gemm_kernel,
                         cudaFuncAttributeMaxDynamicSharedMemorySize, 65536);
    cudaFuncSetAttribute(edge_kernel,
                         cudaFuncAttributeMaxDynamicSharedMemorySize, 172032);

    fps_kernel<<<BB, 512, 131072>>>(xyz, out);
    gather_kernel<<<(BB * CC * SS + 255) / 256, 256>>>(x);
    knn_gemm_kernel<<<dim3(NN / 128, SS / 128, BB), 256, 65536>>>(x);
    topk_kernel<<<BB * SS / 8, 256>>>();
    edge_kernel<<<BB * SS / 16, 256, 172032>>>(x, W0, b0, W1, b1, W2, b2, out);
}